// round 1
// baseline (speedup 1.0000x reference)
#include <cuda_runtime.h>

#define BATCH 512
#define SEQ   512
#define VOCAB 1000
#define EMB   100
#define UNITS 64

typedef unsigned long long ull;

// Scratch: projected embedding table (emb @ Wxh + b), 1000 x 64 fp32 = 256 KB.
__device__ float g_embproj[VOCAB * UNITS];

// ---- packed f32x2 helpers (Blackwell 2xFP32 path, PTX-only) ----
__device__ __forceinline__ ull fma2(ull a, ull b, ull c) {
    ull d;
    asm("fma.rn.f32x2 %0, %1, %2, %3;" : "=l"(d) : "l"(a), "l"(b), "l"(c));
    return d;
}
__device__ __forceinline__ ull add2(ull a, ull b) {
    ull d;
    asm("add.rn.f32x2 %0, %1, %2;" : "=l"(d) : "l"(a), "l"(b));
    return d;
}
__device__ __forceinline__ ull pack2(float lo, float hi) {
    ull d;
    asm("mov.b64 %0, {%1, %2};"
        : "=l"(d) : "r"(__float_as_uint(lo)), "r"(__float_as_uint(hi)));
    return d;
}
__device__ __forceinline__ void unpack2(ull v, float& lo, float& hi) {
    unsigned a, b;
    asm("mov.b64 {%0, %1}, %2;" : "=r"(a), "=r"(b) : "l"(v));
    lo = __uint_as_float(a);
    hi = __uint_as_float(b);
}

// tanh(x) = 1 - 2/(exp(2x)+1). Saturates correctly: exp->inf => 1, exp->0 => -1.
__device__ __forceinline__ float tanh_fast(float x) {
    float e = __expf(2.0f * x);
    return 1.0f - __fdividef(2.0f, e + 1.0f);
}

// ---------------------------------------------------------------------------
// Prologue: embproj[v][u] = sum_d emb[v][d] * Wxh[d][u] + b[u]
// ---------------------------------------------------------------------------
__global__ void k_embproj(const float* __restrict__ emb,
                          const float* __restrict__ Wxh,
                          const float* __restrict__ bias) {
    int v = blockIdx.x;        // vocab id
    int u = threadIdx.x;       // unit
    float acc = bias[u];
    const float* er = emb + v * EMB;
#pragma unroll 4
    for (int d = 0; d < EMB; ++d)
        acc = fmaf(__ldg(er + d), __ldg(Wxh + d * UNITS + u), acc);
    g_embproj[v * UNITS + u] = acc;
}

// ---------------------------------------------------------------------------
// Main: one warp per batch row. Lane l owns units (2l, 2l+1).
// Whh columns held as packed f32x2 register pairs; h broadcast via smem as
// replicated pairs (h[k],h[k]) so the matvec is pure LDS.128 + fma.rn.f32x2.
// ---------------------------------------------------------------------------
__global__ __launch_bounds__(128, 1)
void k_rnn(const int*   __restrict__ tokens,
           const float* __restrict__ Whh,
           const float* __restrict__ Wout,
           const float* __restrict__ bout,
           float*       __restrict__ out) {
    __shared__ __align__(16) ull hs[4][UNITS];   // replicated h pairs per warp
    __shared__ int tok[4][SEQ];

    const int w    = threadIdx.x >> 5;
    const int lane = threadIdx.x & 31;
    const int row  = blockIdx.x * 4 + w;

    // Stage this row's tokens into smem (warp-local, coalesced int4).
    {
        const int4* src = (const int4*)(tokens + row * SEQ);
        int4* dst = (int4*)tok[w];
#pragma unroll
        for (int i = 0; i < 4; ++i)
            dst[lane + 32 * i] = src[lane + 32 * i];
    }

    // Load this lane's two Whh columns as 64 packed pairs (128 regs).
    ull wp[UNITS];
#pragma unroll
    for (int k = 0; k < UNITS; ++k)
        wp[k] = *(const ull*)(Whh + k * UNITS + 2 * lane);

    // h0 = 0
    hs[w][2 * lane]     = 0ull;
    hs[w][2 * lane + 1] = 0ull;
    __syncwarp();

    const float* ep = g_embproj;
    ull* hrow = hs[w];

    // Preload xproj for t=0.
    float2 xt = *(const float2*)(ep + tok[w][0] * UNITS + 2 * lane);

    float h0v = 0.0f, h1v = 0.0f;

    for (int t = 0; t < SEQ; ++t) {
        // Prefetch next step's gathered xproj to hide L2 latency.
        int tn = tok[w][(t + 1 < SEQ) ? t + 1 : SEQ - 1];
        float2 xn = __ldg((const float2*)(ep + tn * UNITS + 2 * lane));

        ull a0 = pack2(xt.x, xt.y), a1 = 0ull, a2 = 0ull, a3 = 0ull;
#pragma unroll
        for (int k = 0; k < UNITS; k += 4) {
            ulonglong2 qa = *(const ulonglong2*)(hrow + k);       // (h[k],h[k]),(h[k+1],h[k+1])
            ulonglong2 qb = *(const ulonglong2*)(hrow + k + 2);
            a0 = fma2(qa.x, wp[k],     a0);
            a1 = fma2(qa.y, wp[k + 1], a1);
            a2 = fma2(qb.x, wp[k + 2], a2);
            a3 = fma2(qb.y, wp[k + 3], a3);
        }
        ull s = add2(add2(a0, a2), add2(a1, a3));
        float s0, s1;
        unpack2(s, s0, s1);
        h0v = tanh_fast(s0);
        h1v = tanh_fast(s1);

        // Publish replicated pairs for next step (STS.128), then warp-fence.
        ulonglong2 st;
        st.x = pack2(h0v, h0v);
        st.y = pack2(h1v, h1v);
        *(ulonglong2*)(hrow + 2 * lane) = st;
        __syncwarp();

        xt = xn;
    }

    // Epilogue: sigmoid(hT @ Wout + bout)
    float2 wo = *(const float2*)(Wout + 2 * lane);
    float part = h0v * wo.x + h1v * wo.y;
#pragma unroll
    for (int o = 16; o; o >>= 1)
        part += __shfl_xor_sync(0xffffffffu, part, o);
    if (lane == 0)
        out[row] = __fdividef(1.0f, 1.0f + __expf(-(part + bout[0])));
}

extern "C" void kernel_launch(void* const* d_in, const int* in_sizes, int n_in,
                              void* d_out, int out_size) {
    const int*   tokens = (const int*)d_in[0];
    const float* emb    = (const float*)d_in[1];
    const float* Wxh    = (const float*)d_in[2];
    const float* Whh    = (const float*)d_in[3];
    const float* b      = (const float*)d_in[4];
    const float* Wout   = (const float*)d_in[5];
    const float* bout   = (const float*)d_in[6];
    float* out = (float*)d_out;

    k_embproj<<<VOCAB, UNITS>>>(emb, Wxh, b);
    k_rnn<<<BATCH / 4, 128>>>(tokens, Whh, Wout, bout, out);
}